// round 2
// baseline (speedup 1.0000x reference)
#include <cuda_runtime.h>
#include <cuda_bf16.h>

#define N_NODES  50000
#define N_EDGES  800000
#define ATOM_DIM 128
#define EDGE_DIM 64

// ---------------- scratch (device globals; no allocation allowed) ----------------
__device__ float g_E[N_EDGES * 256];      // [eS(128) | eG(128)] per edge, bias folded in
__device__ float g_PSrc[N_NODES * 256];   // [sS | gS]  = x @ [Ks[0:128] | Kg[0:128]]
__device__ float g_PDst[N_NODES * 256];   // [sD | gD]  = x @ [Ks[128:256] | Kg[128:256]]
__device__ float g_XA[N_NODES * ATOM_DIM];
__device__ float g_XB[N_NODES * ATOM_DIM];
__device__ int   g_cnt[N_NODES];
__device__ int   g_start[N_NODES + 1];
__device__ int   g_cursor[N_NODES];
__device__ int   g_sDst[N_EDGES];
__device__ int   g_sEid[N_EDGES];

// ---------------- small helpers ----------------
__device__ __forceinline__ float sigf(float x) {
    return __fdividef(1.f, 1.f + __expf(-x));
}
__device__ __forceinline__ float spf(float x) {
    // stable softplus: max(x,0) + log(1 + exp(-|x|))
    return fmaxf(x, 0.f) + __logf(1.f + __expf(-fabsf(x)));
}

// ---------------- CSR build (counting sort by src) ----------------
__global__ void zero_cnt_kernel() {
    int i = blockIdx.x * blockDim.x + threadIdx.x;
    if (i < N_NODES) g_cnt[i] = 0;
}

__global__ void hist_kernel(const int* __restrict__ pair) {
    int e = blockIdx.x * blockDim.x + threadIdx.x;
    if (e < N_EDGES) atomicAdd(&g_cnt[pair[2 * e]], 1);
}

#define SCAN_T 1024
#define SCAN_CHUNK ((N_NODES + SCAN_T - 1) / SCAN_T)
__global__ void scan_kernel() {
    __shared__ int sums[SCAN_T];
    int t = threadIdx.x;
    int lo = t * SCAN_CHUNK;
    int hi = lo + SCAN_CHUNK; if (hi > N_NODES) hi = N_NODES;
    if (lo > N_NODES) lo = N_NODES;
    int s = 0;
    for (int i = lo; i < hi; i++) s += g_cnt[i];
    sums[t] = s;
    __syncthreads();
    for (int off = 1; off < SCAN_T; off <<= 1) {
        int v = 0;
        if (t >= off) v = sums[t - off];
        __syncthreads();
        if (t >= off) sums[t] += v;
        __syncthreads();
    }
    int run = sums[t] - s;  // exclusive prefix
    for (int i = lo; i < hi; i++) {
        g_start[i] = run;
        g_cursor[i] = run;
        run += g_cnt[i];
    }
    if (t == SCAN_T - 1) g_start[N_NODES] = sums[SCAN_T - 1];
}

__global__ void scatter_kernel(const int* __restrict__ pair) {
    int e = blockIdx.x * blockDim.x + threadIdx.x;
    if (e >= N_EDGES) return;
    int s = pair[2 * e];
    int d = pair[2 * e + 1];
    int pos = atomicAdd(&g_cursor[s], 1);
    g_sDst[pos] = d;
    g_sEid[pos] = e;
}

// ---------------- edge-term GEMM: g_E = edges @ [Ks|Kg][256:320] + bias ----------------
// grid: (N_EDGES/128, 2), 256 threads. blockIdx.y: 0 -> s-half (Ks,bias_s), 1 -> g-half (Kg,bias_g)
__global__ void edge_gemm_kernel(const float* __restrict__ edges,
                                 const float* __restrict__ Ks, const float* __restrict__ bs,
                                 const float* __restrict__ Kg, const float* __restrict__ bg) {
    __shared__ float Asm[32][132];  // [k][m] transposed
    __shared__ float Bsm[32][128];  // [k][c]
    int half = blockIdx.y;
    const float* W = half ? Kg : Ks;
    const float* bias = half ? bg : bs;
    int m0 = blockIdx.x * 128;
    int tid = threadIdx.x;
    int cg = tid & 15;   // col group (8 cols)
    int rg = tid >> 4;   // row group (8 rows)

    float acc[8][8];
#pragma unroll
    for (int i = 0; i < 8; i++)
#pragma unroll
        for (int j = 0; j < 8; j++) acc[i][j] = 0.f;

    for (int kc = 0; kc < EDGE_DIM; kc += 32) {
        // A: 128 edges x 32 k -> transpose into Asm
#pragma unroll
        for (int i = 0; i < 4; i++) {
            int idx = tid + i * 256;
            int m = idx >> 3;
            int kq = idx & 7;
            float4 v = *(const float4*)(edges + (long long)(m0 + m) * EDGE_DIM + kc + kq * 4);
            Asm[kq * 4 + 0][m] = v.x;
            Asm[kq * 4 + 1][m] = v.y;
            Asm[kq * 4 + 2][m] = v.z;
            Asm[kq * 4 + 3][m] = v.w;
        }
        // B: 32 rows (W row 256+kc+r) x 128 cols
#pragma unroll
        for (int i = 0; i < 4; i++) {
            int idx = tid + i * 256;
            int r = idx >> 5;
            int cq = idx & 31;
            float4 v = *(const float4*)(W + (256 + kc + r) * 128 + cq * 4);
            *(float4*)&Bsm[r][cq * 4] = v;
        }
        __syncthreads();
#pragma unroll
        for (int k = 0; k < 32; k++) {
            float a[8], b[8];
            *(float4*)&a[0] = *(const float4*)&Asm[k][rg * 8];
            *(float4*)&a[4] = *(const float4*)&Asm[k][rg * 8 + 4];
            *(float4*)&b[0] = *(const float4*)&Bsm[k][cg * 8];
            *(float4*)&b[4] = *(const float4*)&Bsm[k][cg * 8 + 4];
#pragma unroll
            for (int i = 0; i < 8; i++)
#pragma unroll
                for (int j = 0; j < 8; j++) acc[i][j] = fmaf(a[i], b[j], acc[i][j]);
        }
        __syncthreads();
    }
    float bv[8];
#pragma unroll
    for (int j = 0; j < 8; j++) bv[j] = bias[cg * 8 + j];
#pragma unroll
    for (int i = 0; i < 8; i++) {
        long long gm = m0 + rg * 8 + i;
        float* o = g_E + gm * 256 + half * 128 + cg * 8;
        *(float4*)(o)     = make_float4(acc[i][0] + bv[0], acc[i][1] + bv[1], acc[i][2] + bv[2], acc[i][3] + bv[3]);
        *(float4*)(o + 4) = make_float4(acc[i][4] + bv[4], acc[i][5] + bv[5], acc[i][6] + bv[6], acc[i][7] + bv[7]);
    }
}

// ---------------- node GEMM: P{Src,Dst} = x @ W blocks ----------------
// grid: (ceil(N_NODES/128), 4). blockIdx.y: bit0 = which weight (Ks/Kg), bit1 = which row block (src/dst)
__global__ void node_gemm_kernel(const float* __restrict__ Xext,
                                 const float* __restrict__ Ks, const float* __restrict__ Kg,
                                 int xsel) {
    const float* X = (xsel == 0) ? Xext : (xsel == 1 ? g_XA : g_XB);
    int wsel = blockIdx.y & 1;
    int part = blockIdx.y >> 1;
    const float* W = wsel ? Kg : Ks;   // rows part*128 + k
    float* outBase = part ? g_PDst : g_PSrc;
    int colBase = wsel * 128;
    int m0 = blockIdx.x * 128;
    int tid = threadIdx.x;
    int cg = tid & 15;
    int rg = tid >> 4;

    __shared__ float Asm[32][132];
    __shared__ float Bsm[32][128];

    float acc[8][8];
#pragma unroll
    for (int i = 0; i < 8; i++)
#pragma unroll
        for (int j = 0; j < 8; j++) acc[i][j] = 0.f;

    for (int kc = 0; kc < ATOM_DIM; kc += 32) {
#pragma unroll
        for (int i = 0; i < 4; i++) {
            int idx = tid + i * 256;
            int m = idx >> 3;
            int kq = idx & 7;
            int gm = m0 + m;
            float4 v = make_float4(0.f, 0.f, 0.f, 0.f);
            if (gm < N_NODES) v = *(const float4*)(X + (long long)gm * ATOM_DIM + kc + kq * 4);
            Asm[kq * 4 + 0][m] = v.x;
            Asm[kq * 4 + 1][m] = v.y;
            Asm[kq * 4 + 2][m] = v.z;
            Asm[kq * 4 + 3][m] = v.w;
        }
#pragma unroll
        for (int i = 0; i < 4; i++) {
            int idx = tid + i * 256;
            int r = idx >> 5;
            int cq = idx & 31;
            float4 v = *(const float4*)(W + (part * 128 + kc + r) * 128 + cq * 4);
            *(float4*)&Bsm[r][cq * 4] = v;
        }
        __syncthreads();
#pragma unroll
        for (int k = 0; k < 32; k++) {
            float a[8], b[8];
            *(float4*)&a[0] = *(const float4*)&Asm[k][rg * 8];
            *(float4*)&a[4] = *(const float4*)&Asm[k][rg * 8 + 4];
            *(float4*)&b[0] = *(const float4*)&Bsm[k][cg * 8];
            *(float4*)&b[4] = *(const float4*)&Bsm[k][cg * 8 + 4];
#pragma unroll
            for (int i = 0; i < 8; i++)
#pragma unroll
                for (int j = 0; j < 8; j++) acc[i][j] = fmaf(a[i], b[j], acc[i][j]);
        }
        __syncthreads();
    }
#pragma unroll
    for (int i = 0; i < 8; i++) {
        int gm = m0 + rg * 8 + i;
        if (gm < N_NODES) {
            float* o = outBase + (long long)gm * 256 + colBase + cg * 8;
            *(float4*)(o)     = make_float4(acc[i][0], acc[i][1], acc[i][2], acc[i][3]);
            *(float4*)(o + 4) = make_float4(acc[i][4], acc[i][5], acc[i][6], acc[i][7]);
        }
    }
}

// ---------------- fused edge aggregation + activation + node update ----------------
// one warp per node; lane owns 4 features (float4)
__global__ void edge_agg_kernel(const float* __restrict__ Xext_in, int insel,
                                float* __restrict__ Xext_out, int outsel) {
    const float* Xin = (insel == 0) ? Xext_in : (insel == 1 ? g_XA : g_XB);
    float* Xout = (outsel == 0) ? Xext_out : (outsel == 1 ? g_XA : g_XB);

    int gw = (blockIdx.x * blockDim.x + threadIdx.x) >> 5;
    int lane = threadIdx.x & 31;
    if (gw >= N_NODES) return;

    const float4* PS = (const float4*)(g_PSrc) + (long long)gw * 64;
    float4 sS = PS[lane];
    float4 gS = PS[32 + lane];

    float4 acc = make_float4(0.f, 0.f, 0.f, 0.f);
    int beg = g_start[gw];
    int end = g_start[gw + 1];
    for (int i = beg; i < end; i++) {
        int d = g_sDst[i];
        int e = g_sEid[i];
        const float4* PD = (const float4*)(g_PDst) + (long long)d * 64;
        const float4* E  = (const float4*)(g_E)   + (long long)e * 64;
        float4 sD = PD[lane];
        float4 gD = PD[32 + lane];
        float4 eS = E[lane];
        float4 eG = E[32 + lane];
        acc.x += sigf(sS.x + sD.x + eS.x) * spf(gS.x + gD.x + eG.x);
        acc.y += sigf(sS.y + sD.y + eS.y) * spf(gS.y + gD.y + eG.y);
        acc.z += sigf(sS.z + sD.z + eS.z) * spf(gS.z + gD.z + eG.z);
        acc.w += sigf(sS.w + sD.w + eS.w) * spf(gS.w + gD.w + eG.w);
    }
    const float4* xi = (const float4*)(Xin) + (long long)gw * 32;
    float4 xv = xi[lane];
    float4 o = make_float4(spf(xv.x + acc.x), spf(xv.y + acc.y),
                           spf(xv.z + acc.z), spf(xv.w + acc.w));
    ((float4*)(Xout) + (long long)gw * 32)[lane] = o;
}

// ---------------- launch ----------------
extern "C" void kernel_launch(void* const* d_in, const int* in_sizes, int n_in,
                              void* d_out, int out_size) {
    const float* atom  = (const float*)d_in[0];
    const float* edges = (const float*)d_in[1];
    // d_in[2] = state_attrs (unused)
    const float* ks = (const float*)d_in[3];
    const float* bs = (const float*)d_in[4];
    const float* kg = (const float*)d_in[5];
    const float* bg = (const float*)d_in[6];
    const int* pair = (const int*)d_in[7];
    float* out = (float*)d_out;

    // Build CSR (edges grouped by src)
    zero_cnt_kernel<<<(N_NODES + 255) / 256, 256>>>();
    hist_kernel<<<(N_EDGES + 255) / 256, 256>>>(pair);
    scan_kernel<<<1, SCAN_T>>>();
    scatter_kernel<<<(N_EDGES + 255) / 256, 256>>>(pair);

    // Precompute step-invariant edge term (+bias)
    edge_gemm_kernel<<<dim3(N_EDGES / 128, 2), 256>>>(edges, ks, bs, kg, bg);

    dim3 ngrid((N_NODES + 127) / 128, 4);
    int agg_blocks = (N_NODES + 7) / 8;  // 8 warps per 256-thread CTA

    // step 0: x = atom (external) -> g_XA
    node_gemm_kernel<<<ngrid, 256>>>(atom, ks, kg, 0);
    edge_agg_kernel<<<agg_blocks, 256>>>(atom, 0, (float*)d_out, 1);

    // step 1: g_XA -> g_XB
    node_gemm_kernel<<<ngrid, 256>>>(atom, ks, kg, 1);
    edge_agg_kernel<<<agg_blocks, 256>>>(atom, 1, (float*)d_out, 2);

    // step 2: g_XB -> d_out
    node_gemm_kernel<<<ngrid, 256>>>(atom, ks, kg, 2);
    edge_agg_kernel<<<agg_blocks, 256>>>(atom, 2, out, 0);
}